// round 1
// baseline (speedup 1.0000x reference)
#include <cuda_runtime.h>
#include <cuda_bf16.h>

// ---------------------------------------------------------------------------
// Problem constants
// ---------------------------------------------------------------------------
#define Bn  4
#define Sn  1024
#define Dn  1024
#define Hn  16
#define DKn 64

// ---------------------------------------------------------------------------
// Device scratch (allocation-free rule: __device__ globals)
// ---------------------------------------------------------------------------
__device__ float g_q[(size_t)Bn * Hn * Sn * DKn];      // 16 MB  [B,H,S,DK]
__device__ float g_k[(size_t)Bn * Hn * Sn * DKn];      // 16 MB
__device__ float g_v[(size_t)Bn * Hn * Sn * DKn];      // 16 MB
__device__ float g_biasT[(size_t)Bn * Hn * Sn * Sn];   // 256 MB [B,H,S,S]
__device__ float g_ctx[(size_t)Bn * Sn * Dn];          // 16 MB  [B,S,D]
__device__ unsigned char g_mask[Bn * Sn];

// ---------------------------------------------------------------------------
// Helpers
// ---------------------------------------------------------------------------
__device__ __forceinline__ unsigned f2tf32(float x) {
    unsigned r;
    asm("cvt.rna.tf32.f32 %0, %1;" : "=r"(r) : "f"(x));
    return r;
}

__device__ __forceinline__ void mma_tf32(float c[4], const unsigned a[4], const unsigned b[2]) {
    asm volatile(
        "mma.sync.aligned.m16n8k8.row.col.f32.tf32.tf32.f32 "
        "{%0,%1,%2,%3},{%4,%5,%6,%7},{%8,%9},{%0,%1,%2,%3};\n"
        : "+f"(c[0]), "+f"(c[1]), "+f"(c[2]), "+f"(c[3])
        : "r"(a[0]), "r"(a[1]), "r"(a[2]), "r"(a[3]), "r"(b[0]), "r"(b[1]));
}

// ---------------------------------------------------------------------------
// Mask normalization: fingerprint dtype (bool bytes / int32 / float32)
// using only the first 4096 bytes (safe under every hypothesis).
// ---------------------------------------------------------------------------
__global__ void mask_prep_kernel(const void* __restrict__ mraw) {
    __shared__ int flags[2]; // [0]: not-int32, [1]: not-float32
    if (threadIdx.x < 2) flags[threadIdx.x] = 0;
    __syncthreads();
    const unsigned* w = (const unsigned*)mraw;
    for (int i = threadIdx.x; i < 1024; i += blockDim.x) {
        unsigned v = w[i];
        if (v > 1u) flags[0] = 1;
        if (v != 0u && v != 0x3F800000u) flags[1] = 1;
    }
    __syncthreads();
    int mode = flags[0] ? (flags[1] ? 0 : 2) : 1; // 0=bytes, 1=int32, 2=float32
    for (int i = threadIdx.x; i < Bn * Sn; i += blockDim.x) {
        unsigned char v;
        if (mode == 1)      v = (((const int*)mraw)[i] != 0);
        else if (mode == 2) v = (((const float*)mraw)[i] != 0.f);
        else                v = (((const unsigned char*)mraw)[i] != 0);
        g_mask[i] = v;
    }
}

// ---------------------------------------------------------------------------
// Bias transpose [B,S,S,H] -> [B,H,S,S], fully coalesced both sides.
// grid (S/128, S, B), block 256. Each CTA moves a 128(k) x 16(h) sub-tile.
// ---------------------------------------------------------------------------
__global__ void bias_tr_kernel(const float* __restrict__ bias) {
    __shared__ float t[16][129];
    const int k0 = blockIdx.x * 128;
    const int q  = blockIdx.y;
    const int b  = blockIdx.z;
    const float* src = bias + ((size_t)(b * Sn + q) * Sn + k0) * Hn;
    for (int i = threadIdx.x; i < 2048; i += 256) {
        int kk = i >> 4, hh = i & 15;
        t[hh][kk] = src[i];
    }
    __syncthreads();
    for (int i = threadIdx.x; i < 2048; i += 256) {
        int hh = i >> 7, kk = i & 127;
        g_biasT[((size_t)(b * Hn + hh) * Sn + q) * Sn + k0 + kk] = t[hh][kk];
    }
}

// ---------------------------------------------------------------------------
// TN GEMM core: C[M,N] = A[M,K=1024] * W[N,K=1024]^T + bias[n]
// CTA tile 128x128x32, 256 threads (8 warps, 2(m) x 4(n), warp tile 64x32),
// tf32 mma.sync m16n8k8, single-buffered smem with register staging.
// MODE 0: out row-major [M, 1024].   MODE 1: out [B,H,S,DK] (QKV layout).
// ---------------------------------------------------------------------------
template <int MODE>
__device__ __forceinline__ void gemm_tn_128(const float* __restrict__ A,
                                            const float* __restrict__ W,
                                            const float* __restrict__ bvec,
                                            float* __restrict__ out) {
    __shared__ unsigned sA[128 * 36];
    __shared__ unsigned sW[128 * 36];

    const int tid  = threadIdx.x;
    const int lane = tid & 31;
    const int warp = tid >> 5;
    const int wm = (warp >> 2) * 64;   // 0 / 64
    const int wn = (warp & 3) * 32;    // 0 / 32 / 64 / 96
    const int m0 = blockIdx.y * 128;
    const int n0 = blockIdx.x * 128;

    float acc[4][4][4];
#pragma unroll
    for (int mt = 0; mt < 4; mt++)
#pragma unroll
        for (int nt = 0; nt < 4; nt++)
#pragma unroll
            for (int j = 0; j < 4; j++) acc[mt][nt][j] = 0.f;

    float4 ra[4], rw[4];
#pragma unroll
    for (int i = 0; i < 4; i++) {
        int task = i * 256 + tid;
        int row = task >> 3, c4 = task & 7;
        ra[i] = *(const float4*)(A + (size_t)(m0 + row) * Dn + c4 * 4);
        rw[i] = *(const float4*)(W + (size_t)(n0 + row) * Dn + c4 * 4);
    }

    for (int kt = 0; kt < 32; kt++) {
#pragma unroll
        for (int i = 0; i < 4; i++) {
            int task = i * 256 + tid;
            int row = task >> 3, c4 = task & 7;
            unsigned* pA = &sA[row * 36 + c4 * 4];
            pA[0] = f2tf32(ra[i].x); pA[1] = f2tf32(ra[i].y);
            pA[2] = f2tf32(ra[i].z); pA[3] = f2tf32(ra[i].w);
            unsigned* pW = &sW[row * 36 + c4 * 4];
            pW[0] = f2tf32(rw[i].x); pW[1] = f2tf32(rw[i].y);
            pW[2] = f2tf32(rw[i].z); pW[3] = f2tf32(rw[i].w);
        }
        __syncthreads();

        if (kt < 31) {
            int kb = (kt + 1) * 32;
#pragma unroll
            for (int i = 0; i < 4; i++) {
                int task = i * 256 + tid;
                int row = task >> 3, c4 = task & 7;
                ra[i] = *(const float4*)(A + (size_t)(m0 + row) * Dn + kb + c4 * 4);
                rw[i] = *(const float4*)(W + (size_t)(n0 + row) * Dn + kb + c4 * 4);
            }
        }

#pragma unroll
        for (int ks = 0; ks < 4; ks++) {
            const int kk = ks * 8;
            unsigned afr[4][4];
#pragma unroll
            for (int mt = 0; mt < 4; mt++) {
                int r = wm + mt * 16 + (lane >> 2);
                int c = kk + (lane & 3);
                afr[mt][0] = sA[r * 36 + c];
                afr[mt][1] = sA[(r + 8) * 36 + c];
                afr[mt][2] = sA[r * 36 + c + 4];
                afr[mt][3] = sA[(r + 8) * 36 + c + 4];
            }
            unsigned bfr[4][2];
#pragma unroll
            for (int nt = 0; nt < 4; nt++) {
                int r = wn + nt * 8 + (lane >> 2);
                int c = kk + (lane & 3);
                bfr[nt][0] = sW[r * 36 + c];
                bfr[nt][1] = sW[r * 36 + c + 4];
            }
#pragma unroll
            for (int mt = 0; mt < 4; mt++)
#pragma unroll
                for (int nt = 0; nt < 4; nt++)
                    mma_tf32(acc[mt][nt], afr[mt], bfr[nt]);
        }
        __syncthreads();
    }

    // Epilogue
#pragma unroll
    for (int mt = 0; mt < 4; mt++) {
#pragma unroll
        for (int nt = 0; nt < 4; nt++) {
            int row = m0 + wm + mt * 16 + (lane >> 2);
            int col = n0 + wn + nt * 8 + ((lane & 3) << 1);
            float b0 = bvec[col], b1 = bvec[col + 1];
            float2 v0 = make_float2(acc[mt][nt][0] + b0, acc[mt][nt][1] + b1);
            float2 v1 = make_float2(acc[mt][nt][2] + b0, acc[mt][nt][3] + b1);
            if (MODE == 0) {
                *(float2*)(out + (size_t)row * Dn + col) = v0;
                *(float2*)(out + (size_t)(row + 8) * Dn + col) = v1;
            } else {
                int hh = col >> 6, dk = col & 63;
                int bb0 = row >> 10, s0 = row & 1023;
                int r8 = row + 8;
                int bb1 = r8 >> 10, s1 = r8 & 1023;
                *(float2*)(out + ((size_t)(bb0 * Hn + hh) * Sn + s0) * DKn + dk) = v0;
                *(float2*)(out + ((size_t)(bb1 * Hn + hh) * Sn + s1) * DKn + dk) = v1;
            }
        }
    }
}

// One launch covers all three projections via grid.z.
__global__ void __launch_bounds__(256) qkv_proj_kernel(
    const float* __restrict__ Xq, const float* __restrict__ Xk, const float* __restrict__ Xv,
    const float* __restrict__ Wq, const float* __restrict__ Wk, const float* __restrict__ Wv,
    const float* __restrict__ bq, const float* __restrict__ bk, const float* __restrict__ bv) {
    int z = blockIdx.z;
    const float* A = (z == 0) ? Xq : (z == 1) ? Xk : Xv;
    const float* W = (z == 0) ? Wq : (z == 1) ? Wk : Wv;
    const float* bb = (z == 0) ? bq : (z == 1) ? bk : bv;
    float* out = (z == 0) ? g_q : (z == 1) ? g_k : g_v;
    gemm_tn_128<1>(A, W, bb, out);
}

__global__ void __launch_bounds__(256) outproj_kernel(
    const float* __restrict__ Wo, const float* __restrict__ bo, float* __restrict__ out) {
    gemm_tn_128<0>(g_ctx, Wo, bo, out);
}

// ---------------------------------------------------------------------------
// Flash attention: CTA = (q-tile of 64, head, batch). 128 threads (4 warps),
// warp owns 16 q-rows. kv tiles of 64, online softmax, tf32 mma for QK^T & PV.
// ---------------------------------------------------------------------------
#define SQS 68   // stride (floats) for sQ / sKP
#define SVS 72   // stride for sV (bank-clean for B-frag reads)
#define SMEM_ATTN ((64 * SQS * 2 + 64 * SVS) * 4 + 128)

__global__ void __launch_bounds__(128) attn_kernel() {
    extern __shared__ unsigned char smraw[];
    unsigned* sQ  = (unsigned*)smraw;
    unsigned* sKP = sQ + 64 * SQS;          // K tile, reused as P tile
    unsigned* sV  = sKP + 64 * SQS;
    unsigned char* smk = (unsigned char*)(sV + 64 * SVS);

    const int qt = blockIdx.x, h = blockIdx.y, b = blockIdx.z;
    const int q0 = qt * 64;
    const int tid = threadIdx.x, lane = tid & 31, warp = tid >> 5;
    const int rq = warp * 16 + (lane >> 2);  // first local q-row of this thread

    const size_t headoff = (size_t)(b * Hn + h) * Sn * DKn;
    const float* Qg = g_q + headoff + (size_t)q0 * DKn;
    const float* Kg = g_k + headoff;
    const float* Vg = g_v + headoff;
    const float* Bg = g_biasT + ((size_t)(b * Hn + h) * Sn + q0) * Sn;
    const unsigned char* Mg = g_mask + b * Sn;

    // Load Q tile (tf32)
#pragma unroll
    for (int i = 0; i < 8; i++) {
        int task = i * 128 + tid;
        int row = task >> 4, c4 = task & 15;
        float4 v = *(const float4*)(Qg + (size_t)row * DKn + c4 * 4);
        uint4 t = make_uint4(f2tf32(v.x), f2tf32(v.y), f2tf32(v.z), f2tf32(v.w));
        *(uint4*)&sQ[row * SQS + c4 * 4] = t;
    }

    const int mq0 = Mg[q0 + rq];
    const int mq1 = Mg[q0 + rq + 8];

    float mrow0 = -1e30f, mrow1 = -1e30f, lrow0 = 0.f, lrow1 = 0.f;
    float o[8][4];
#pragma unroll
    for (int nt = 0; nt < 8; nt++)
#pragma unroll
        for (int j = 0; j < 4; j++) o[nt][j] = 0.f;

    for (int kt = 0; kt < 16; kt++) {
        const int kv0 = kt * 64;
        __syncthreads();  // sKP / sV free for reuse

        // Load K and V tiles (tf32)
#pragma unroll
        for (int i = 0; i < 8; i++) {
            int task = i * 128 + tid;
            int row = task >> 4, c4 = task & 15;
            float4 kv = *(const float4*)(Kg + (size_t)(kv0 + row) * DKn + c4 * 4);
            *(uint4*)&sKP[row * SQS + c4 * 4] =
                make_uint4(f2tf32(kv.x), f2tf32(kv.y), f2tf32(kv.z), f2tf32(kv.w));
            float4 vv = *(const float4*)(Vg + (size_t)(kv0 + row) * DKn + c4 * 4);
            *(uint4*)&sV[row * SVS + c4 * 4] =
                make_uint4(f2tf32(vv.x), f2tf32(vv.y), f2tf32(vv.z), f2tf32(vv.w));
        }
        if (tid < 64) smk[tid] = Mg[kv0 + tid];
        __syncthreads();

        // Prefetch bias (the 256 MB stream) while tensor pipe works
        float2 bb0[8], bb1[8];
#pragma unroll
        for (int nt = 0; nt < 8; nt++) {
            int col = nt * 8 + ((lane & 3) << 1);
            bb0[nt] = *(const float2*)(Bg + (size_t)rq * Sn + kv0 + col);
            bb1[nt] = *(const float2*)(Bg + (size_t)(rq + 8) * Sn + kv0 + col);
        }

        // S = Q K^T
        float s[8][4];
#pragma unroll
        for (int nt = 0; nt < 8; nt++)
#pragma unroll
            for (int j = 0; j < 4; j++) s[nt][j] = 0.f;

#pragma unroll
        for (int ks = 0; ks < 8; ks++) {
            const int kk = ks * 8;
            unsigned afr[4];
            {
                int c = kk + (lane & 3);
                afr[0] = sQ[rq * SQS + c];
                afr[1] = sQ[(rq + 8) * SQS + c];
                afr[2] = sQ[rq * SQS + c + 4];
                afr[3] = sQ[(rq + 8) * SQS + c + 4];
            }
#pragma unroll
            for (int nt = 0; nt < 8; nt++) {
                unsigned bfr[2];
                int r = nt * 8 + (lane >> 2);
                int c = kk + (lane & 3);
                bfr[0] = sKP[r * SQS + c];
                bfr[1] = sKP[r * SQS + c + 4];
                mma_tf32(s[nt], afr, bfr);
            }
        }

        // bias + scale + mask
        float rmax0 = -1e30f, rmax1 = -1e30f;
#pragma unroll
        for (int nt = 0; nt < 8; nt++) {
            int col = nt * 8 + ((lane & 3) << 1);
            int k0ok = smk[col], k1ok = smk[col + 1];
            float v0 = (mq0 & k0ok) ? (s[nt][0] + bb0[nt].x) * 0.125f : -1e9f;
            float v1 = (mq0 & k1ok) ? (s[nt][1] + bb0[nt].y) * 0.125f : -1e9f;
            float v2 = (mq1 & k0ok) ? (s[nt][2] + bb1[nt].x) * 0.125f : -1e9f;
            float v3 = (mq1 & k1ok) ? (s[nt][3] + bb1[nt].y) * 0.125f : -1e9f;
            s[nt][0] = v0; s[nt][1] = v1; s[nt][2] = v2; s[nt][3] = v3;
            rmax0 = fmaxf(rmax0, fmaxf(v0, v1));
            rmax1 = fmaxf(rmax1, fmaxf(v2, v3));
        }
        rmax0 = fmaxf(rmax0, __shfl_xor_sync(0xffffffffu, rmax0, 1));
        rmax0 = fmaxf(rmax0, __shfl_xor_sync(0xffffffffu, rmax0, 2));
        rmax1 = fmaxf(rmax1, __shfl_xor_sync(0xffffffffu, rmax1, 1));
        rmax1 = fmaxf(rmax1, __shfl_xor_sync(0xffffffffu, rmax1, 2));

        float mnew0 = fmaxf(mrow0, rmax0), mnew1 = fmaxf(mrow1, rmax1);
        float alpha0 = __expf(mrow0 - mnew0), alpha1 = __expf(mrow1 - mnew1);
        mrow0 = mnew0; mrow1 = mnew1;

        float sum0 = 0.f, sum1 = 0.f;
#pragma unroll
        for (int nt = 0; nt < 8; nt++) {
            s[nt][0] = __expf(s[nt][0] - mnew0); sum0 += s[nt][0];
            s[nt][1] = __expf(s[nt][1] - mnew0); sum0 += s[nt][1];
            s[nt][2] = __expf(s[nt][2] - mnew1); sum1 += s[nt][2];
            s[nt][3] = __expf(s[nt][3] - mnew1); sum1 += s[nt][3];
        }
        sum0 += __shfl_xor_sync(0xffffffffu, sum0, 1);
        sum0 += __shfl_xor_sync(0xffffffffu, sum0, 2);
        sum1 += __shfl_xor_sync(0xffffffffu, sum1, 1);
        sum1 += __shfl_xor_sync(0xffffffffu, sum1, 2);
        lrow0 = lrow0 * alpha0 + sum0;
        lrow1 = lrow1 * alpha1 + sum1;

#pragma unroll
        for (int nt = 0; nt < 8; nt++) {
            o[nt][0] *= alpha0; o[nt][1] *= alpha0;
            o[nt][2] *= alpha1; o[nt][3] *= alpha1;
        }

        __syncthreads();  // all warps done reading sKP (K) -> overwrite with P
#pragma unroll
        for (int nt = 0; nt < 8; nt++) {
            int col = nt * 8 + ((lane & 3) << 1);
            *(uint2*)&sKP[rq * SQS + col] =
                make_uint2(f2tf32(s[nt][0]), f2tf32(s[nt][1]));
            *(uint2*)&sKP[(rq + 8) * SQS + col] =
                make_uint2(f2tf32(s[nt][2]), f2tf32(s[nt][3]));
        }
        __syncthreads();

        // O += P V
#pragma unroll
        for (int ks = 0; ks < 8; ks++) {
            const int kk = ks * 8;
            unsigned afr[4];
            {
                int c = kk + (lane & 3);
                afr[0] = sKP[rq * SQS + c];
                afr[1] = sKP[(rq + 8) * SQS + c];
                afr[2] = sKP[rq * SQS + c + 4];
                afr[3] = sKP[(rq + 8) * SQS + c + 4];
            }
#pragma unroll
            for (int nt = 0; nt < 8; nt++) {
                unsigned bfr[2];
                int n = nt * 8 + (lane >> 2);
                bfr[0] = sV[(kk + (lane & 3)) * SVS + n];
                bfr[1] = sV[(kk + 4 + (lane & 3)) * SVS + n];
                mma_tf32(o[nt], afr, bfr);
            }
        }
    }

    // Epilogue: normalize and write ctx[b, q, h*64 + dk]
    float inv0 = 1.f / lrow0, inv1 = 1.f / lrow1;
    float* Cg = g_ctx + ((size_t)b * Sn + q0) * Dn + h * DKn;
#pragma unroll
    for (int nt = 0; nt < 8; nt++) {
        int col = nt * 8 + ((lane & 3) << 1);
        *(float2*)(Cg + (size_t)rq * Dn + col) =
            make_float2(o[nt][0] * inv0, o[nt][1] * inv0);
        *(float2*)(Cg + (size_t)(rq + 8) * Dn + col) =
            make_float2(o[nt][2] * inv1, o[nt][3] * inv1);
    }
}

// ---------------------------------------------------------------------------
// kernel_launch
// Inputs: 0 query, 1 key, 2 value, 3 attention_bias, 4 mask,
//         5 Wq, 6 bq, 7 Wk, 8 bk, 9 Wv, 10 bv, 11 Wo, 12 bo
// ---------------------------------------------------------------------------
extern "C" void kernel_launch(void* const* d_in, const int* in_sizes, int n_in,
                              void* d_out, int out_size) {
    (void)in_sizes; (void)n_in; (void)out_size;
    const float* query = (const float*)d_in[0];
    const float* key   = (const float*)d_in[1];
    const float* value = (const float*)d_in[2];
    const float* bias  = (const float*)d_in[3];
    const void*  mask  = d_in[4];
    const float* Wq = (const float*)d_in[5];
    const float* bq = (const float*)d_in[6];
    const float* Wk = (const float*)d_in[7];
    const float* bk = (const float*)d_in[8];
    const float* Wv = (const float*)d_in[9];
    const float* bv = (const float*)d_in[10];
    const float* Wo = (const float*)d_in[11];
    const float* bo = (const float*)d_in[12];
    float* out = (float*)d_out;

    cudaFuncSetAttribute(attn_kernel, cudaFuncAttributeMaxDynamicSharedMemorySize,
                         SMEM_ATTN);

    mask_prep_kernel<<<1, 256>>>(mask);
    bias_tr_kernel<<<dim3(Sn / 128, Sn, Bn), 256>>>(bias);
    qkv_proj_kernel<<<dim3(Dn / 128, (Bn * Sn) / 128, 3), 256>>>(
        query, key, value, Wq, Wk, Wv, bq, bk, bv);
    attn_kernel<<<dim3(Sn / 64, Hn, Bn), 128, SMEM_ATTN>>>();
    outproj_kernel<<<dim3(Dn / 128, (Bn * Sn) / 128, 1), 256>>>(Wo, bo, out);
}